// round 15
// baseline (speedup 1.0000x reference)
#include <cuda_runtime.h>
#include <cstdint>

#define Nn   16
#define Cc   256
#define HWn  4608
#define Sn   64
#define SPLIT 18
#define KCH  (HWn / SPLIT)   // 256
#define NT   128
#define NTILE (HWn / NT)     // 36
#define CNT  ((float)Nn * (float)HWn)

// ---------------- scratch (device globals; no allocs allowed) ----------------
__device__ __align__(16) float g_xs [Nn * Sn * HWn];
__device__ __align__(16) float g_t  [Nn * Sn * HWn];          // raw gated t; k3g overwrites with comb
__device__ __align__(16) float g_xnp[Nn * SPLIT * 128 * 64];  // [xn; G] split-K partials
__device__ __align__(16) float g_M  [Nn * Cc * Sn];
__device__ __align__(16) float g_pm [Nn * NTILE * Sn];
__device__ __align__(16) float g_ps [Nn * NTILE * Sn];
__device__ float g_s1[Nn * Cc];
__device__ float g_s2[Nn * Cc];

// ---------------- helpers ----------------
__device__ __forceinline__ uint32_t smem_u32(const void* p) {
    uint32_t a;
    asm("{ .reg .u64 t; cvta.to.shared.u64 t, %1; cvt.u32.u64 %0, t; }" : "=r"(a) : "l"(p));
    return a;
}
__device__ __forceinline__ void mma_tf32(float* d, const uint32_t* a, const uint32_t* b) {
    asm volatile(
        "mma.sync.aligned.m16n8k8.row.col.f32.tf32.tf32.f32 "
        "{%0,%1,%2,%3}, {%4,%5,%6,%7}, {%8,%9}, {%0,%1,%2,%3};"
        : "+f"(d[0]), "+f"(d[1]), "+f"(d[2]), "+f"(d[3])
        : "r"(a[0]), "r"(a[1]), "r"(a[2]), "r"(a[3]), "r"(b[0]), "r"(b[1]));
}
__device__ __forceinline__ void cp16(uint32_t dst, const void* src) {
    asm volatile("cp.async.ca.shared.global [%0], [%1], 16;" :: "r"(dst), "l"(src));
}
#define CP_COMMIT()  asm volatile("cp.async.commit_group;" ::: "memory")
#define CP_WAIT0()   asm volatile("cp.async.wait_group 0;" ::: "memory")
#define CP_WAIT1()   asm volatile("cp.async.wait_group 1;" ::: "memory")
#define FU(x) __float_as_uint(x)

#define SA_STRIDE 36
#define SB_STRIDE 136
// dynamic smem float offsets
#define OFF_A0 0
#define OFF_A1 4608
#define OFF_B0 9216
#define OFF_B1 13568
#define GEMM_SMEM_FLOATS 17920
#define K1_SMEM_BYTES (GEMM_SMEM_FLOATS * 4)
#define K7_SMEM_BYTES ((GEMM_SMEM_FLOATS + 256) * 4)

// ================= k1: [xs;t](128 x 128cols) = [Ws;Wp](128x256) @ x-tile ============
__global__ void __launch_bounds__(256) k1_mma(
    const float* __restrict__ x, const float* __restrict__ edge,
    const float* __restrict__ Ws, const float* __restrict__ bs,
    const float* __restrict__ Wp, const float* __restrict__ bp)
{
    extern __shared__ float smf[];
    const int n = blockIdx.y, tileX = blockIdx.x, k0 = tileX * NT;
    const int tid = threadIdx.x, wid = tid >> 5, lane = tid & 31;
    const int wm = wid >> 2, wn = wid & 3;
    const int g = lane >> 2, t4 = lane & 3;
    const uint32_t sb = smem_u32(smf);
    float acc[4][4][4] = {};
    const float* xb = x + (size_t)n * Cc * HWn + k0;

    auto issueA = [&](int ch, int buf) {
        const uint32_t base = sb + (buf ? OFF_A1 : OFF_A0) * 4;
        #pragma unroll
        for (int it = 0; it < 4; it++) {
            int idx = tid + it * 256;
            int m = idx >> 3, k4 = idx & 7;
            const float* src = ((m < 64) ? (Ws + m * 256) : (Wp + (m - 64) * 256))
                               + ch * 32 + k4 * 4;
            cp16(base + (uint32_t)(m * SA_STRIDE + k4 * 4) * 4, src);
        }
    };
    auto issueB = [&](int ch, int buf) {
        const uint32_t base = sb + (buf ? OFF_B1 : OFF_B0) * 4;
        #pragma unroll
        for (int it = 0; it < 4; it++) {
            int idx = tid + it * 256;
            int k = idx >> 5, n4 = idx & 31;
            cp16(base + (uint32_t)(k * SB_STRIDE + n4 * 4) * 4,
                 xb + (size_t)(ch * 32 + k) * HWn + n4 * 4);
        }
    };

    issueA(0, 0); issueB(0, 0); CP_COMMIT();

    #pragma unroll 1
    for (int ch = 0; ch < 8; ch++) {
        if (ch < 7) { issueA(ch + 1, (ch + 1) & 1); issueB(ch + 1, (ch + 1) & 1); CP_COMMIT(); CP_WAIT1(); }
        else CP_WAIT0();
        __syncthreads();
        const float* fA = smf + ((ch & 1) ? OFF_A1 : OFF_A0);
        const float* fB = smf + ((ch & 1) ? OFF_B1 : OFF_B0);
        #pragma unroll
        for (int ks = 0; ks < 4; ks++) {
            const int kb = ks * 8;
            uint32_t a[4][4], b[4][2];
            #pragma unroll
            for (int mt = 0; mt < 4; mt++) {
                int m = wm * 64 + mt * 16;
                a[mt][0] = FU(fA[(m + g) * SA_STRIDE + kb + t4]);
                a[mt][1] = FU(fA[(m + g + 8) * SA_STRIDE + kb + t4]);
                a[mt][2] = FU(fA[(m + g) * SA_STRIDE + kb + t4 + 4]);
                a[mt][3] = FU(fA[(m + g + 8) * SA_STRIDE + kb + t4 + 4]);
            }
            #pragma unroll
            for (int nt = 0; nt < 4; nt++) {
                int nn = wn * 32 + nt * 8;
                b[nt][0] = FU(fB[(kb + t4) * SB_STRIDE + nn + g]);
                b[nt][1] = FU(fB[(kb + t4 + 4) * SB_STRIDE + nn + g]);
            }
            #pragma unroll
            for (int mt = 0; mt < 4; mt++)
                #pragma unroll
                for (int nt = 0; nt < 4; nt++)
                    mma_tf32(acc[mt][nt], a[mt], b[nt]);
        }
        __syncthreads();
    }

    const int nbase = k0 + wn * 32 + 2 * t4;
    float* sPm = smf;          // [4][64]
    float* sPs = smf + 256;    // [4][64]

    if (wm == 0) {
        #pragma unroll
        for (int mt = 0; mt < 4; mt++) {
            int s0 = mt * 16 + g;
            float bv0 = bs[s0], bv1 = bs[s0 + 8];
            float* r0p = g_xs + (size_t)(n * 64 + s0) * HWn;
            float* r1p = r0p + (size_t)8 * HWn;
            #pragma unroll
            for (int nt = 0; nt < 4; nt++) {
                int col = nbase + nt * 8;
                *(float2*)(r0p + col) = make_float2(acc[mt][nt][0] + bv0, acc[mt][nt][1] + bv0);
                *(float2*)(r1p + col) = make_float2(acc[mt][nt][2] + bv1, acc[mt][nt][3] + bv1);
            }
        }
    } else {
        const float* e0p = edge + (size_t)(n * 2) * HWn;
        const float* e1p = e0p + HWn;
        float2 gate[4];
        #pragma unroll
        for (int nt = 0; nt < 4; nt++) {
            int col = nbase + nt * 8;
            float2 e0 = *(const float2*)(e0p + col);
            float2 e1 = *(const float2*)(e1p + col);
            gate[nt].x = 2.0f - 1.0f / (1.0f + __expf(e1.x - e0.x));
            gate[nt].y = 2.0f - 1.0f / (1.0f + __expf(e1.y - e0.y));
        }
        #pragma unroll
        for (int mt = 0; mt < 4; mt++) {
            int s0 = mt * 16 + g;
            float bv0 = bp[s0], bv1 = bp[s0 + 8];
            float* r0p = g_t + (size_t)(n * 64 + s0) * HWn;
            float* r1p = r0p + (size_t)8 * HWn;
            float mA = -1e30f, mB = -1e30f;
            #pragma unroll
            for (int nt = 0; nt < 4; nt++) {
                int col = nbase + nt * 8;
                float v0 = (acc[mt][nt][0] + bv0) * gate[nt].x;
                float v1 = (acc[mt][nt][1] + bv0) * gate[nt].y;
                float v2 = (acc[mt][nt][2] + bv1) * gate[nt].x;
                float v3 = (acc[mt][nt][3] + bv1) * gate[nt].y;
                acc[mt][nt][0] = v0; acc[mt][nt][1] = v1;
                acc[mt][nt][2] = v2; acc[mt][nt][3] = v3;
                *(float2*)(r0p + col) = make_float2(v0, v1);
                *(float2*)(r1p + col) = make_float2(v2, v3);
                mA = fmaxf(mA, fmaxf(v0, v1));
                mB = fmaxf(mB, fmaxf(v2, v3));
            }
            mA = fmaxf(mA, __shfl_xor_sync(0xffffffffu, mA, 1));
            mA = fmaxf(mA, __shfl_xor_sync(0xffffffffu, mA, 2));
            mB = fmaxf(mB, __shfl_xor_sync(0xffffffffu, mB, 1));
            mB = fmaxf(mB, __shfl_xor_sync(0xffffffffu, mB, 2));
            if (t4 == 0) { sPm[wn * 64 + s0] = mA; sPm[wn * 64 + s0 + 8] = mB; }
        }
    }
    __syncthreads();
    if (wm == 1) {
        #pragma unroll
        for (int mt = 0; mt < 4; mt++) {
            int rA = mt * 16 + g, rB = rA + 8;
            float MA = fmaxf(fmaxf(sPm[rA], sPm[64 + rA]), fmaxf(sPm[128 + rA], sPm[192 + rA]));
            float MB = fmaxf(fmaxf(sPm[rB], sPm[64 + rB]), fmaxf(sPm[128 + rB], sPm[192 + rB]));
            float sA = 0.f, sB = 0.f;
            #pragma unroll
            for (int nt = 0; nt < 4; nt++) {
                sA += __expf(acc[mt][nt][0] - MA) + __expf(acc[mt][nt][1] - MA);
                sB += __expf(acc[mt][nt][2] - MB) + __expf(acc[mt][nt][3] - MB);
            }
            sA += __shfl_xor_sync(0xffffffffu, sA, 1);
            sA += __shfl_xor_sync(0xffffffffu, sA, 2);
            sB += __shfl_xor_sync(0xffffffffu, sB, 1);
            sB += __shfl_xor_sync(0xffffffffu, sB, 2);
            if (t4 == 0) { sPs[wn * 64 + rA] = sA; sPs[wn * 64 + rB] = sB; }
        }
    }
    __syncthreads();
    if (wm == 1 && wn == 0 && t4 == 0) {
        #pragma unroll
        for (int mt = 0; mt < 4; mt++) {
            #pragma unroll
            for (int h = 0; h < 2; h++) {
                int r = mt * 16 + g + h * 8;
                float M = fmaxf(fmaxf(sPm[r], sPm[64 + r]), fmaxf(sPm[128 + r], sPm[192 + r]));
                float S = sPs[r] + sPs[64 + r] + sPs[128 + r] + sPs[192 + r];
                g_pm[(size_t)(n * NTILE + tileX) * 64 + r] = M;
                g_ps[(size_t)(n * NTILE + tileX) * 64 + r] = S;
            }
        }
    }
}

// ================= k3g: [xn; G] = [xs; comb](128xK) @ comb(64xK)^T, split-K ==========
// register-staged double buffering; writes exp-normalized comb back to g_t in place.
__global__ void __launch_bounds__(256) k3g_mma()
{
    __shared__ float sA[64 * SA_STRIDE];
    __shared__ float sB[64 * SA_STRIDE];
    __shared__ float sPm4[4][64], sPs4[4][64];
    __shared__ float sRm[64], sRi[64];
    const int sp = blockIdx.x, n = blockIdx.y;
    const int koff = sp * KCH;
    const int tid = threadIdx.x, wid = tid >> 5, lane = tid & 31;
    const int wm = wid >> 1, wn = wid & 1;      // 4 x 2 warps
    const int g = lane >> 2, t4 = lane & 3;

    {
        int s = tid & 63, part = tid >> 6;
        float mt9[9];
        float Mp = -1e30f;
        #pragma unroll
        for (int t = 0; t < 9; t++) {
            mt9[t] = g_pm[(size_t)(n * NTILE + part * 9 + t) * 64 + s];
            Mp = fmaxf(Mp, mt9[t]);
        }
        float Sp = 0.f;
        #pragma unroll
        for (int t = 0; t < 9; t++)
            Sp += g_ps[(size_t)(n * NTILE + part * 9 + t) * 64 + s] * __expf(mt9[t] - Mp);
        sPm4[part][s] = Mp; sPs4[part][s] = Sp;
    }
    __syncthreads();
    if (tid < 64) {
        float M = fmaxf(fmaxf(sPm4[0][tid], sPm4[1][tid]), fmaxf(sPm4[2][tid], sPm4[3][tid]));
        float S = sPs4[0][tid] * __expf(sPm4[0][tid] - M) + sPs4[1][tid] * __expf(sPm4[1][tid] - M)
                + sPs4[2][tid] * __expf(sPm4[2][tid] - M) + sPs4[3][tid] * __expf(sPm4[3][tid] - M);
        sRm[tid] = M;
        sRi[tid] = 1.0f / S;
    }
    __syncthreads();

    float acc[2][4][4] = {};
    const float* A = g_xs + (size_t)n * Sn * HWn + koff;
    float* B = g_t + (size_t)n * Sn * HWn + koff;
    const float* srcA = (wm < 2) ? sA : sB;
    const int mloc = (wm & 1) * 32;

    const int m0 = tid >> 3,          k40 = (tid & 7) * 4;
    const int m1 = (tid + 256) >> 3,  k41 = ((tid + 256) & 7) * 4;
    const float Mr0 = sRm[m0], Ir0 = sRi[m0];
    const float Mr1 = sRm[m1], Ir1 = sRi[m1];

    float4 ra0 = *(const float4*)(A + (size_t)m0 * HWn + k40);
    float4 rb0 = *(const float4*)(B + (size_t)m0 * HWn + k40);
    float4 ra1 = *(const float4*)(A + (size_t)m1 * HWn + k41);
    float4 rb1 = *(const float4*)(B + (size_t)m1 * HWn + k41);

    #pragma unroll 1
    for (int ch = 0; ch < KCH / 32; ch++) {
        const int c0 = ch * 32;
        {
            float4 tb0 = {__expf(rb0.x - Mr0) * Ir0, __expf(rb0.y - Mr0) * Ir0,
                          __expf(rb0.z - Mr0) * Ir0, __expf(rb0.w - Mr0) * Ir0};
            float4 tb1 = {__expf(rb1.x - Mr1) * Ir1, __expf(rb1.y - Mr1) * Ir1,
                          __expf(rb1.z - Mr1) * Ir1, __expf(rb1.w - Mr1) * Ir1};
            *(float4*)&sA[m0 * SA_STRIDE + k40] = ra0;
            *(float4*)&sB[m0 * SA_STRIDE + k40] = tb0;
            *(float4*)&sA[m1 * SA_STRIDE + k41] = ra1;
            *(float4*)&sB[m1 * SA_STRIDE + k41] = tb1;
            *(float4*)(B + (size_t)m0 * HWn + c0 + k40) = tb0;
            *(float4*)(B + (size_t)m1 * HWn + c0 + k41) = tb1;
        }
        __syncthreads();
        if (ch < KCH / 32 - 1) {
            const int c1 = (ch + 1) * 32;
            ra0 = *(const float4*)(A + (size_t)m0 * HWn + c1 + k40);
            rb0 = *(const float4*)(B + (size_t)m0 * HWn + c1 + k40);
            ra1 = *(const float4*)(A + (size_t)m1 * HWn + c1 + k41);
            rb1 = *(const float4*)(B + (size_t)m1 * HWn + c1 + k41);
        }
        #pragma unroll
        for (int ks = 0; ks < 4; ks++) {
            const int kb = ks * 8;
            uint32_t a[2][4], b[4][2];
            #pragma unroll
            for (int mt = 0; mt < 2; mt++) {
                int m = mloc + mt * 16;
                a[mt][0] = FU(srcA[(m + g) * SA_STRIDE + kb + t4]);
                a[mt][1] = FU(srcA[(m + g + 8) * SA_STRIDE + kb + t4]);
                a[mt][2] = FU(srcA[(m + g) * SA_STRIDE + kb + t4 + 4]);
                a[mt][3] = FU(srcA[(m + g + 8) * SA_STRIDE + kb + t4 + 4]);
            }
            #pragma unroll
            for (int nt = 0; nt < 4; nt++) {
                int nn = wn * 32 + nt * 8;
                b[nt][0] = FU(sB[(nn + g) * SA_STRIDE + kb + t4]);
                b[nt][1] = FU(sB[(nn + g) * SA_STRIDE + kb + t4 + 4]);
            }
            #pragma unroll
            for (int mt = 0; mt < 2; mt++)
                #pragma unroll
                for (int nt = 0; nt < 4; nt++)
                    mma_tf32(acc[mt][nt], a[mt], b[nt]);
        }
        __syncthreads();
    }

    float* dst = g_xnp + (size_t)(n * SPLIT + sp) * 8192;
    #pragma unroll
    for (int mt = 0; mt < 2; mt++) {
        int r = wm * 32 + mt * 16 + g;
        #pragma unroll
        for (int nt = 0; nt < 4; nt++) {
            int t = wn * 32 + nt * 8 + 2 * t4;
            *(float2*)(dst + r * 64 + t)       = make_float2(acc[mt][nt][0], acc[mt][nt][1]);
            *(float2*)(dst + (r + 8) * 64 + t) = make_float2(acc[mt][nt][2], acc[mt][nt][3]);
        }
    }
}

// ================= k4f: fused GCN + M + BN partials ================
#define S68 68
#define K4F_SMEM ((3 * 64 * S68 + 128 * S68) * 4)   // 87040 B
__global__ void __launch_bounds__(256) k4f(
    const float* __restrict__ W1, const float* __restrict__ W2,
    const float* __restrict__ We)
{
    extern __shared__ float sm[];
    float* sXn = sm;
    float* sG  = sm + 64 * S68;
    float* sHT = sm + 2 * 64 * S68;
    float* sMb = sm + 3 * 64 * S68;
    const int n = blockIdx.x;
    const int tid = threadIdx.x, wid = tid >> 5, lane = tid & 31;
    const int g = lane >> 2, t4 = lane & 3;

    #pragma unroll
    for (int it = 0; it < 4; it++) {
        int idx = tid + it * 256;
        int row = idx >> 4, col = (idx & 15) * 4;
        float4 sx = {0.f,0.f,0.f,0.f}, sg = {0.f,0.f,0.f,0.f};
        #pragma unroll
        for (int p = 0; p < SPLIT; p++) {
            const float* base = g_xnp + (size_t)(n * SPLIT + p) * 8192;
            float4 a = *(const float4*)(base + row * 64 + col);
            float4 b = *(const float4*)(base + 4096 + row * 64 + col);
            sx.x += a.x; sx.y += a.y; sx.z += a.z; sx.w += a.w;
            sg.x += b.x; sg.y += b.y; sg.z += b.z; sg.w += b.w;
        }
        *(float4*)&sXn[row * S68 + col] = sx;
        *(float4*)&sG [row * S68 + col] = sg;
    }
    __syncthreads();

    {
        const int wm = wid >> 2, wn = wid & 3;
        float hacc[2][2][4] = {};
        #pragma unroll
        for (int ks = 0; ks < 8; ks++) {
            const int kb = ks * 8;
            uint32_t a[2][4], b[2][2];
            #pragma unroll
            for (int mt = 0; mt < 2; mt++) {
                int m = wm * 32 + mt * 16;
                a[mt][0] = FU(sXn[(m + g) * S68 + kb + t4]);
                a[mt][1] = FU(sXn[(m + g + 8) * S68 + kb + t4]);
                a[mt][2] = FU(sXn[(m + g) * S68 + kb + t4 + 4]);
                a[mt][3] = FU(sXn[(m + g + 8) * S68 + kb + t4 + 4]);
            }
            #pragma unroll
            for (int nt = 0; nt < 2; nt++) {
                int nn = wn * 16 + nt * 8;
                b[nt][0] = FU(__ldg(&W1[(nn + g) * 64 + kb + t4]));
                b[nt][1] = FU(__ldg(&W1[(nn + g) * 64 + kb + t4 + 4]));
            }
            #pragma unroll
            for (int mt = 0; mt < 2; mt++)
                #pragma unroll
                for (int nt = 0; nt < 2; nt++)
                    mma_tf32(hacc[mt][nt], a[mt], b[nt]);
        }
        #pragma unroll
        for (int mt = 0; mt < 2; mt++) {
            int s0 = wm * 32 + mt * 16 + g;
            #pragma unroll
            for (int nt = 0; nt < 2; nt++) {
                int i0 = wn * 16 + nt * 8 + 2 * t4;
                sHT[i0 * S68 + s0]           = hacc[mt][nt][0] - sXn[s0 * S68 + i0];
                sHT[(i0 + 1) * S68 + s0]     = hacc[mt][nt][1] - sXn[s0 * S68 + i0 + 1];
                sHT[i0 * S68 + s0 + 8]       = hacc[mt][nt][2] - sXn[(s0 + 8) * S68 + i0];
                sHT[(i0 + 1) * S68 + s0 + 8] = hacc[mt][nt][3] - sXn[(s0 + 8) * S68 + i0 + 1];
            }
        }
    }
    __syncthreads();

    {
        const int wm = wid >> 2, wn = wid & 3;
        float hacc[2][2][4] = {};
        #pragma unroll
        for (int ks = 0; ks < 8; ks++) {
            const int kb = ks * 8;
            uint32_t a[2][4], b[2][2];
            #pragma unroll
            for (int mt = 0; mt < 2; mt++) {
                int m = wm * 32 + mt * 16;
                a[mt][0] = FU(__ldg(&W2[(m + g) * 64 + kb + t4]));
                a[mt][1] = FU(__ldg(&W2[(m + g + 8) * 64 + kb + t4]));
                a[mt][2] = FU(__ldg(&W2[(m + g) * 64 + kb + t4 + 4]));
                a[mt][3] = FU(__ldg(&W2[(m + g + 8) * 64 + kb + t4 + 4]));
            }
            #pragma unroll
            for (int nt = 0; nt < 2; nt++) {
                int nn = wn * 16 + nt * 8;
                b[nt][0] = FU(sHT[(nn + g) * S68 + kb + t4]);
                b[nt][1] = FU(sHT[(nn + g) * S68 + kb + t4 + 4]);
            }
            #pragma unroll
            for (int mt = 0; mt < 2; mt++)
                #pragma unroll
                for (int nt = 0; nt < 2; nt++)
                    mma_tf32(hacc[mt][nt], a[mt], b[nt]);
        }
        __syncthreads();
        #pragma unroll
        for (int mt = 0; mt < 2; mt++) {
            int i0 = wm * 32 + mt * 16 + g;
            #pragma unroll
            for (int nt = 0; nt < 2; nt++) {
                int k = wn * 16 + nt * 8 + 2 * t4;
                sXn[i0 * S68 + k]           = fmaxf(hacc[mt][nt][0], 0.f);
                sXn[i0 * S68 + k + 1]       = fmaxf(hacc[mt][nt][1], 0.f);
                sXn[(i0 + 8) * S68 + k]     = fmaxf(hacc[mt][nt][2], 0.f);
                sXn[(i0 + 8) * S68 + k + 1] = fmaxf(hacc[mt][nt][3], 0.f);
            }
        }
    }
    __syncthreads();

    #pragma unroll 1
    for (int bnd = 0; bnd < 2; bnd++) {
        const int rloc = 16 * wid;
        const int c0 = bnd * 128 + rloc;
        float macc[8][4] = {}, racc[8][4] = {};
        #pragma unroll
        for (int ks = 0; ks < 8; ks++) {
            const int kb = ks * 8;
            uint32_t a[4], b[8][2];
            a[0] = FU(__ldg(&We[(c0 + g) * 64 + kb + t4]));
            a[1] = FU(__ldg(&We[(c0 + g + 8) * 64 + kb + t4]));
            a[2] = FU(__ldg(&We[(c0 + g) * 64 + kb + t4 + 4]));
            a[3] = FU(__ldg(&We[(c0 + g + 8) * 64 + kb + t4 + 4]));
            #pragma unroll
            for (int nt = 0; nt < 8; nt++) {
                b[nt][0] = FU(sXn[(kb + t4) * S68 + nt * 8 + g]);
                b[nt][1] = FU(sXn[(kb + t4 + 4) * S68 + nt * 8 + g]);
            }
            #pragma unroll
            for (int nt = 0; nt < 8; nt++)
                mma_tf32(macc[nt], a, b[nt]);
        }
        float* Mg = g_M + (size_t)n * Cc * Sn;
        #pragma unroll
        for (int nt = 0; nt < 8; nt++) {
            int col = nt * 8 + 2 * t4;
            *(float2*)(Mg + (c0 + g) * 64 + col)     = make_float2(macc[nt][0], macc[nt][1]);
            *(float2*)(Mg + (c0 + g + 8) * 64 + col) = make_float2(macc[nt][2], macc[nt][3]);
            sMb[(rloc + g) * S68 + col]     = macc[nt][0];
            sMb[(rloc + g) * S68 + col + 1] = macc[nt][1];
            sMb[(rloc + g + 8) * S68 + col]     = macc[nt][2];
            sMb[(rloc + g + 8) * S68 + col + 1] = macc[nt][3];
        }
        __syncthreads();
        #pragma unroll
        for (int ks = 0; ks < 8; ks++) {
            const int kb = ks * 8;
            uint32_t a[4], b[8][2];
            a[0] = FU(sMb[(rloc + g) * S68 + kb + t4]);
            a[1] = FU(sMb[(rloc + g + 8) * S68 + kb + t4]);
            a[2] = FU(sMb[(rloc + g) * S68 + kb + t4 + 4]);
            a[3] = FU(sMb[(rloc + g + 8) * S68 + kb + t4 + 4]);
            #pragma unroll
            for (int nt = 0; nt < 8; nt++) {
                b[nt][0] = FU(sG[(nt * 8 + g) * S68 + kb + t4]);
                b[nt][1] = FU(sG[(nt * 8 + g) * S68 + kb + t4 + 4]);
            }
            #pragma unroll
            for (int nt = 0; nt < 8; nt++)
                mma_tf32(racc[nt], a, b[nt]);
        }
        float s10 = 0.f, s11 = 0.f, s20 = 0.f, s21 = 0.f;
        #pragma unroll
        for (int nt = 0; nt < 8; nt++) {
            s10 += macc[nt][0] + macc[nt][1];
            s11 += macc[nt][2] + macc[nt][3];
            s20 += macc[nt][0] * racc[nt][0] + macc[nt][1] * racc[nt][1];
            s21 += macc[nt][2] * racc[nt][2] + macc[nt][3] * racc[nt][3];
        }
        s10 += __shfl_xor_sync(0xffffffffu, s10, 1); s10 += __shfl_xor_sync(0xffffffffu, s10, 2);
        s11 += __shfl_xor_sync(0xffffffffu, s11, 1); s11 += __shfl_xor_sync(0xffffffffu, s11, 2);
        s20 += __shfl_xor_sync(0xffffffffu, s20, 1); s20 += __shfl_xor_sync(0xffffffffu, s20, 2);
        s21 += __shfl_xor_sync(0xffffffffu, s21, 1); s21 += __shfl_xor_sync(0xffffffffu, s21, 2);
        if (t4 == 0) {
            g_s1[n * Cc + c0 + g] = s10;     g_s2[n * Cc + c0 + g] = s20;
            g_s1[n * Cc + c0 + g + 8] = s11; g_s2[n * Cc + c0 + g + 8] = s21;
        }
        __syncthreads();
    }
}

// ================= k7g: out = x + BN(M(128x64) @ comb-tile(64x128)) ==================
// R11 shape; x reads via __ldg, out stores streaming (__stcs) to protect L2.
__global__ void __launch_bounds__(256) k7g_mma(
    const float* __restrict__ x, const float* __restrict__ gamma,
    const float* __restrict__ beta, float* __restrict__ out)
{
    extern __shared__ float smf[];
    float* sMean = smf + GEMM_SMEM_FLOATS;        // [128]
    float* sIstd = sMean + 128;                   // [128]
    const int n = blockIdx.z, band = blockIdx.y, tileX = blockIdx.x;
    const int r0 = band * 128, k0 = tileX * NT;
    const int tid = threadIdx.x, wid = tid >> 5, lane = tid & 31;
    const int wm = wid >> 2, wn = wid & 3;
    const int g = lane >> 2, t4 = lane & 3;
    const uint32_t sb = smem_u32(smf);
    float acc[4][4][4] = {};
    const float* Mb = g_M + (size_t)n * Cc * Sn;
    const float* Cb = g_t + (size_t)n * Sn * HWn + k0;

    #pragma unroll
    for (int ch = 0; ch < 2; ch++) {
        const uint32_t base = sb + (ch ? OFF_A1 : OFF_A0) * 4;
        #pragma unroll
        for (int it = 0; it < 4; it++) {
            int idx = tid + it * 256;
            int m = idx >> 3, k4 = idx & 7;
            cp16(base + (uint32_t)(m * SA_STRIDE + k4 * 4) * 4,
                 Mb + (size_t)(r0 + m) * 64 + ch * 32 + k4 * 4);
        }
    }
    #pragma unroll
    for (int ch = 0; ch < 2; ch++) {
        const uint32_t base = sb + (ch ? OFF_B1 : OFF_B0) * 4;
        #pragma unroll
        for (int it = 0; it < 4; it++) {
            int idx = tid + it * 256;
            int k = idx >> 5, n4 = idx & 31;
            cp16(base + (uint32_t)(k * SB_STRIDE + n4 * 4) * 4,
                 Cb + (size_t)(ch * 32 + k) * HWn + n4 * 4);
        }
    }
    CP_COMMIT();
    if (tid < 128) {
        int c = r0 + tid;
        float s = 0.f, q = 0.f;
        #pragma unroll
        for (int nn = 0; nn < Nn; nn++) { s += g_s1[nn * Cc + c]; q += g_s2[nn * Cc + c]; }
        float mean = s / CNT;
        float var = q / CNT - mean * mean;
        sMean[tid] = mean;
        sIstd[tid] = rsqrtf(var + 1e-5f);
    }
    CP_WAIT0();
    __syncthreads();

    #pragma unroll
    for (int ch = 0; ch < 2; ch++) {
        const float* fA = smf + (ch ? OFF_A1 : OFF_A0);
        const float* fB = smf + (ch ? OFF_B1 : OFF_B0);
        #pragma unroll
        for (int ks = 0; ks < 4; ks++) {
            const int kb = ks * 8;
            uint32_t a[4][4], b[4][2];
            #pragma unroll
            for (int mt = 0; mt < 4; mt++) {
                int m = wm * 64 + mt * 16;
                a[mt][0] = FU(fA[(m + g) * SA_STRIDE + kb + t4]);
                a[mt][1] = FU(fA[(m + g + 8) * SA_STRIDE + kb + t4]);
                a[mt][2] = FU(fA[(m + g) * SA_STRIDE + kb + t4 + 4]);
                a[mt][3] = FU(fA[(m + g + 8) * SA_STRIDE + kb + t4 + 4]);
            }
            #pragma unroll
            for (int nt = 0; nt < 4; nt++) {
                int nn = wn * 32 + nt * 8;
                b[nt][0] = FU(fB[(kb + t4) * SB_STRIDE + nn + g]);
                b[nt][1] = FU(fB[(kb + t4 + 4) * SB_STRIDE + nn + g]);
            }
            #pragma unroll
            for (int mt = 0; mt < 4; mt++)
                #pragma unroll
                for (int nt = 0; nt < 4; nt++)
                    mma_tf32(acc[mt][nt], a[mt], b[nt]);
        }
    }

    const int nbase = k0 + wn * 32 + 2 * t4;
    #pragma unroll
    for (int mt = 0; mt < 4; mt++) {
        int lA = wm * 64 + mt * 16 + g;
        int cA = r0 + lA, cB = cA + 8;
        float gA = gamma[cA] * sIstd[lA],     bA = beta[cA] - sMean[lA] * gA;
        float gB = gamma[cB] * sIstd[lA + 8], bB = beta[cB] - sMean[lA + 8] * gB;
        const float2* x0p = (const float2*)(x + (size_t)(n * Cc + cA) * HWn);
        const float2* x1p = (const float2*)(x + (size_t)(n * Cc + cB) * HWn);
        float2* o0p = (float2*)(out + (size_t)(n * Cc + cA) * HWn);
        float2* o1p = (float2*)(out + (size_t)(n * Cc + cB) * HWn);
        #pragma unroll
        for (int nt = 0; nt < 4; nt++) {
            int col2 = (nbase + nt * 8) >> 1;
            float2 xv0 = __ldg(x0p + col2);
            float2 xv1 = __ldg(x1p + col2);
            __stcs(o0p + col2, make_float2(xv0.x + acc[mt][nt][0] * gA + bA,
                                           xv0.y + acc[mt][nt][1] * gA + bA));
            __stcs(o1p + col2, make_float2(xv1.x + acc[mt][nt][2] * gB + bB,
                                           xv1.y + acc[mt][nt][3] * gB + bB));
        }
    }
}

// ---------------- launch ----------------
extern "C" void kernel_launch(void* const* d_in, const int* in_sizes, int n_in,
                              void* d_out, int out_size)
{
    const float* x     = (const float*)d_in[0];
    const float* edge  = (const float*)d_in[1];
    const float* Ws    = (const float*)d_in[2];
    const float* bs    = (const float*)d_in[3];
    const float* Wp    = (const float*)d_in[4];
    const float* bp    = (const float*)d_in[5];
    const float* W1    = (const float*)d_in[6];
    const float* W2    = (const float*)d_in[7];
    const float* We    = (const float*)d_in[8];
    const float* gamma = (const float*)d_in[9];
    const float* beta  = (const float*)d_in[10];
    float* out = (float*)d_out;

    cudaFuncSetAttribute(k1_mma,  cudaFuncAttributeMaxDynamicSharedMemorySize, K1_SMEM_BYTES);
    cudaFuncSetAttribute(k4f,     cudaFuncAttributeMaxDynamicSharedMemorySize, K4F_SMEM);
    cudaFuncSetAttribute(k7g_mma, cudaFuncAttributeMaxDynamicSharedMemorySize, K7_SMEM_BYTES);

    k1_mma <<<dim3(NTILE, Nn), 256, K1_SMEM_BYTES>>>(x, edge, Ws, bs, Wp, bp);
    k3g_mma<<<dim3(SPLIT, Nn), 256>>>();
    k4f    <<<Nn, 256, K4F_SMEM>>>(W1, W2, We);
    k7g_mma<<<dim3(NTILE, 2, Nn), 256, K7_SMEM_BYTES>>>(x, gamma, beta, out);
}

// round 16
// speedup vs baseline: 1.0953x; 1.0953x over previous
#include <cuda_runtime.h>
#include <cstdint>

#define Nn   16
#define Cc   256
#define HWn  4608
#define Sn   64
#define SPLIT 18
#define KCH  (HWn / SPLIT)   // 256
#define NT   128
#define NTILE (HWn / NT)     // 36
#define CNT  ((float)Nn * (float)HWn)

// ---------------- scratch (device globals; no allocs allowed) ----------------
__device__ __align__(16) float g_xs [Nn * Sn * HWn];
__device__ __align__(16) float g_t  [Nn * Sn * HWn];          // raw gated t; k3g overwrites with comb
__device__ __align__(16) float g_xnp[Nn * SPLIT * 128 * 64];  // [xn; G] split-K partials
__device__ __align__(16) float g_M  [Nn * Cc * Sn];
__device__ __align__(16) float g_pm [Nn * NTILE * Sn];
__device__ __align__(16) float g_ps [Nn * NTILE * Sn];
__device__ float g_s1[Nn * Cc];
__device__ float g_s2[Nn * Cc];

// ---------------- helpers ----------------
__device__ __forceinline__ uint32_t smem_u32(const void* p) {
    uint32_t a;
    asm("{ .reg .u64 t; cvta.to.shared.u64 t, %1; cvt.u32.u64 %0, t; }" : "=r"(a) : "l"(p));
    return a;
}
__device__ __forceinline__ void mma_tf32(float* d, const uint32_t* a, const uint32_t* b) {
    asm volatile(
        "mma.sync.aligned.m16n8k8.row.col.f32.tf32.tf32.f32 "
        "{%0,%1,%2,%3}, {%4,%5,%6,%7}, {%8,%9}, {%0,%1,%2,%3};"
        : "+f"(d[0]), "+f"(d[1]), "+f"(d[2]), "+f"(d[3])
        : "r"(a[0]), "r"(a[1]), "r"(a[2]), "r"(a[3]), "r"(b[0]), "r"(b[1]));
}
__device__ __forceinline__ void cp16(uint32_t dst, const void* src) {
    asm volatile("cp.async.ca.shared.global [%0], [%1], 16;" :: "r"(dst), "l"(src));
}
#define CP_COMMIT()  asm volatile("cp.async.commit_group;" ::: "memory")
#define CP_WAIT0()   asm volatile("cp.async.wait_group 0;" ::: "memory")
#define CP_WAIT1()   asm volatile("cp.async.wait_group 1;" ::: "memory")
#define FU(x) __float_as_uint(x)

#define SA_STRIDE 36
#define SB_STRIDE 136
// dynamic smem float offsets
#define OFF_A0 0
#define OFF_A1 4608
#define OFF_B0 9216
#define OFF_B1 13568
#define GEMM_SMEM_FLOATS 17920
#define K1_SMEM_BYTES (GEMM_SMEM_FLOATS * 4)
#define K7_SMEM_BYTES ((GEMM_SMEM_FLOATS + 256) * 4)

// ================= k1: [xs;t](128 x 128cols) = [Ws;Wp](128x256) @ x-tile ============
__global__ void __launch_bounds__(256) k1_mma(
    const float* __restrict__ x, const float* __restrict__ edge,
    const float* __restrict__ Ws, const float* __restrict__ bs,
    const float* __restrict__ Wp, const float* __restrict__ bp)
{
    extern __shared__ float smf[];
    const int n = blockIdx.y, tileX = blockIdx.x, k0 = tileX * NT;
    const int tid = threadIdx.x, wid = tid >> 5, lane = tid & 31;
    const int wm = wid >> 2, wn = wid & 3;
    const int g = lane >> 2, t4 = lane & 3;
    const uint32_t sb = smem_u32(smf);
    float acc[4][4][4] = {};
    const float* xb = x + (size_t)n * Cc * HWn + k0;

    auto issueA = [&](int ch, int buf) {
        const uint32_t base = sb + (buf ? OFF_A1 : OFF_A0) * 4;
        #pragma unroll
        for (int it = 0; it < 4; it++) {
            int idx = tid + it * 256;
            int m = idx >> 3, k4 = idx & 7;
            const float* src = ((m < 64) ? (Ws + m * 256) : (Wp + (m - 64) * 256))
                               + ch * 32 + k4 * 4;
            cp16(base + (uint32_t)(m * SA_STRIDE + k4 * 4) * 4, src);
        }
    };
    auto issueB = [&](int ch, int buf) {
        const uint32_t base = sb + (buf ? OFF_B1 : OFF_B0) * 4;
        #pragma unroll
        for (int it = 0; it < 4; it++) {
            int idx = tid + it * 256;
            int k = idx >> 5, n4 = idx & 31;
            cp16(base + (uint32_t)(k * SB_STRIDE + n4 * 4) * 4,
                 xb + (size_t)(ch * 32 + k) * HWn + n4 * 4);
        }
    };

    issueA(0, 0); issueB(0, 0); CP_COMMIT();

    #pragma unroll 1
    for (int ch = 0; ch < 8; ch++) {
        if (ch < 7) { issueA(ch + 1, (ch + 1) & 1); issueB(ch + 1, (ch + 1) & 1); CP_COMMIT(); CP_WAIT1(); }
        else CP_WAIT0();
        __syncthreads();
        const float* fA = smf + ((ch & 1) ? OFF_A1 : OFF_A0);
        const float* fB = smf + ((ch & 1) ? OFF_B1 : OFF_B0);
        #pragma unroll
        for (int ks = 0; ks < 4; ks++) {
            const int kb = ks * 8;
            uint32_t a[4][4], b[4][2];
            #pragma unroll
            for (int mt = 0; mt < 4; mt++) {
                int m = wm * 64 + mt * 16;
                a[mt][0] = FU(fA[(m + g) * SA_STRIDE + kb + t4]);
                a[mt][1] = FU(fA[(m + g + 8) * SA_STRIDE + kb + t4]);
                a[mt][2] = FU(fA[(m + g) * SA_STRIDE + kb + t4 + 4]);
                a[mt][3] = FU(fA[(m + g + 8) * SA_STRIDE + kb + t4 + 4]);
            }
            #pragma unroll
            for (int nt = 0; nt < 4; nt++) {
                int nn = wn * 32 + nt * 8;
                b[nt][0] = FU(fB[(kb + t4) * SB_STRIDE + nn + g]);
                b[nt][1] = FU(fB[(kb + t4 + 4) * SB_STRIDE + nn + g]);
            }
            #pragma unroll
            for (int mt = 0; mt < 4; mt++)
                #pragma unroll
                for (int nt = 0; nt < 4; nt++)
                    mma_tf32(acc[mt][nt], a[mt], b[nt]);
        }
        __syncthreads();
    }

    const int nbase = k0 + wn * 32 + 2 * t4;
    float* sPm = smf;          // [4][64]
    float* sPs = smf + 256;    // [4][64]

    if (wm == 0) {
        #pragma unroll
        for (int mt = 0; mt < 4; mt++) {
            int s0 = mt * 16 + g;
            float bv0 = bs[s0], bv1 = bs[s0 + 8];
            float* r0p = g_xs + (size_t)(n * 64 + s0) * HWn;
            float* r1p = r0p + (size_t)8 * HWn;
            #pragma unroll
            for (int nt = 0; nt < 4; nt++) {
                int col = nbase + nt * 8;
                *(float2*)(r0p + col) = make_float2(acc[mt][nt][0] + bv0, acc[mt][nt][1] + bv0);
                *(float2*)(r1p + col) = make_float2(acc[mt][nt][2] + bv1, acc[mt][nt][3] + bv1);
            }
        }
    } else {
        const float* e0p = edge + (size_t)(n * 2) * HWn;
        const float* e1p = e0p + HWn;
        float2 gate[4];
        #pragma unroll
        for (int nt = 0; nt < 4; nt++) {
            int col = nbase + nt * 8;
            float2 e0 = *(const float2*)(e0p + col);
            float2 e1 = *(const float2*)(e1p + col);
            gate[nt].x = 2.0f - 1.0f / (1.0f + __expf(e1.x - e0.x));
            gate[nt].y = 2.0f - 1.0f / (1.0f + __expf(e1.y - e0.y));
        }
        #pragma unroll
        for (int mt = 0; mt < 4; mt++) {
            int s0 = mt * 16 + g;
            float bv0 = bp[s0], bv1 = bp[s0 + 8];
            float* r0p = g_t + (size_t)(n * 64 + s0) * HWn;
            float* r1p = r0p + (size_t)8 * HWn;
            float mA = -1e30f, mB = -1e30f;
            #pragma unroll
            for (int nt = 0; nt < 4; nt++) {
                int col = nbase + nt * 8;
                float v0 = (acc[mt][nt][0] + bv0) * gate[nt].x;
                float v1 = (acc[mt][nt][1] + bv0) * gate[nt].y;
                float v2 = (acc[mt][nt][2] + bv1) * gate[nt].x;
                float v3 = (acc[mt][nt][3] + bv1) * gate[nt].y;
                acc[mt][nt][0] = v0; acc[mt][nt][1] = v1;
                acc[mt][nt][2] = v2; acc[mt][nt][3] = v3;
                *(float2*)(r0p + col) = make_float2(v0, v1);
                *(float2*)(r1p + col) = make_float2(v2, v3);
                mA = fmaxf(mA, fmaxf(v0, v1));
                mB = fmaxf(mB, fmaxf(v2, v3));
            }
            mA = fmaxf(mA, __shfl_xor_sync(0xffffffffu, mA, 1));
            mA = fmaxf(mA, __shfl_xor_sync(0xffffffffu, mA, 2));
            mB = fmaxf(mB, __shfl_xor_sync(0xffffffffu, mB, 1));
            mB = fmaxf(mB, __shfl_xor_sync(0xffffffffu, mB, 2));
            if (t4 == 0) { sPm[wn * 64 + s0] = mA; sPm[wn * 64 + s0 + 8] = mB; }
        }
    }
    __syncthreads();
    if (wm == 1) {
        #pragma unroll
        for (int mt = 0; mt < 4; mt++) {
            int rA = mt * 16 + g, rB = rA + 8;
            float MA = fmaxf(fmaxf(sPm[rA], sPm[64 + rA]), fmaxf(sPm[128 + rA], sPm[192 + rA]));
            float MB = fmaxf(fmaxf(sPm[rB], sPm[64 + rB]), fmaxf(sPm[128 + rB], sPm[192 + rB]));
            float sA = 0.f, sB = 0.f;
            #pragma unroll
            for (int nt = 0; nt < 4; nt++) {
                sA += __expf(acc[mt][nt][0] - MA) + __expf(acc[mt][nt][1] - MA);
                sB += __expf(acc[mt][nt][2] - MB) + __expf(acc[mt][nt][3] - MB);
            }
            sA += __shfl_xor_sync(0xffffffffu, sA, 1);
            sA += __shfl_xor_sync(0xffffffffu, sA, 2);
            sB += __shfl_xor_sync(0xffffffffu, sB, 1);
            sB += __shfl_xor_sync(0xffffffffu, sB, 2);
            if (t4 == 0) { sPs[wn * 64 + rA] = sA; sPs[wn * 64 + rB] = sB; }
        }
    }
    __syncthreads();
    if (wm == 1 && wn == 0 && t4 == 0) {
        #pragma unroll
        for (int mt = 0; mt < 4; mt++) {
            #pragma unroll
            for (int h = 0; h < 2; h++) {
                int r = mt * 16 + g + h * 8;
                float M = fmaxf(fmaxf(sPm[r], sPm[64 + r]), fmaxf(sPm[128 + r], sPm[192 + r]));
                float S = sPs[r] + sPs[64 + r] + sPs[128 + r] + sPs[192 + r];
                g_pm[(size_t)(n * NTILE + tileX) * 64 + r] = M;
                g_ps[(size_t)(n * NTILE + tileX) * 64 + r] = S;
            }
        }
    }
}

// ================= k3g: [xn; G] = [xs; comb](128xK) @ comb(64xK)^T, split-K ==========
// register-staged double buffering; writes exp-normalized comb back to g_t in place.
__global__ void __launch_bounds__(256) k3g_mma()
{
    __shared__ float sA[64 * SA_STRIDE];
    __shared__ float sB[64 * SA_STRIDE];
    __shared__ float sPm4[4][64], sPs4[4][64];
    __shared__ float sRm[64], sRi[64];
    const int sp = blockIdx.x, n = blockIdx.y;
    const int koff = sp * KCH;
    const int tid = threadIdx.x, wid = tid >> 5, lane = tid & 31;
    const int wm = wid >> 1, wn = wid & 1;      // 4 x 2 warps
    const int g = lane >> 2, t4 = lane & 3;

    {
        int s = tid & 63, part = tid >> 6;
        float mt9[9];
        float Mp = -1e30f;
        #pragma unroll
        for (int t = 0; t < 9; t++) {
            mt9[t] = g_pm[(size_t)(n * NTILE + part * 9 + t) * 64 + s];
            Mp = fmaxf(Mp, mt9[t]);
        }
        float Sp = 0.f;
        #pragma unroll
        for (int t = 0; t < 9; t++)
            Sp += g_ps[(size_t)(n * NTILE + part * 9 + t) * 64 + s] * __expf(mt9[t] - Mp);
        sPm4[part][s] = Mp; sPs4[part][s] = Sp;
    }
    __syncthreads();
    if (tid < 64) {
        float M = fmaxf(fmaxf(sPm4[0][tid], sPm4[1][tid]), fmaxf(sPm4[2][tid], sPm4[3][tid]));
        float S = sPs4[0][tid] * __expf(sPm4[0][tid] - M) + sPs4[1][tid] * __expf(sPm4[1][tid] - M)
                + sPs4[2][tid] * __expf(sPm4[2][tid] - M) + sPs4[3][tid] * __expf(sPm4[3][tid] - M);
        sRm[tid] = M;
        sRi[tid] = 1.0f / S;
    }
    __syncthreads();

    float acc[2][4][4] = {};
    const float* A = g_xs + (size_t)n * Sn * HWn + koff;
    float* B = g_t + (size_t)n * Sn * HWn + koff;
    const float* srcA = (wm < 2) ? sA : sB;
    const int mloc = (wm & 1) * 32;

    const int m0 = tid >> 3,          k40 = (tid & 7) * 4;
    const int m1 = (tid + 256) >> 3,  k41 = ((tid + 256) & 7) * 4;
    const float Mr0 = sRm[m0], Ir0 = sRi[m0];
    const float Mr1 = sRm[m1], Ir1 = sRi[m1];

    float4 ra0 = *(const float4*)(A + (size_t)m0 * HWn + k40);
    float4 rb0 = *(const float4*)(B + (size_t)m0 * HWn + k40);
    float4 ra1 = *(const float4*)(A + (size_t)m1 * HWn + k41);
    float4 rb1 = *(const float4*)(B + (size_t)m1 * HWn + k41);

    #pragma unroll 1
    for (int ch = 0; ch < KCH / 32; ch++) {
        const int c0 = ch * 32;
        {
            float4 tb0 = {__expf(rb0.x - Mr0) * Ir0, __expf(rb0.y - Mr0) * Ir0,
                          __expf(rb0.z - Mr0) * Ir0, __expf(rb0.w - Mr0) * Ir0};
            float4 tb1 = {__expf(rb1.x - Mr1) * Ir1, __expf(rb1.y - Mr1) * Ir1,
                          __expf(rb1.z - Mr1) * Ir1, __expf(rb1.w - Mr1) * Ir1};
            *(float4*)&sA[m0 * SA_STRIDE + k40] = ra0;
            *(float4*)&sB[m0 * SA_STRIDE + k40] = tb0;
            *(float4*)&sA[m1 * SA_STRIDE + k41] = ra1;
            *(float4*)&sB[m1 * SA_STRIDE + k41] = tb1;
            *(float4*)(B + (size_t)m0 * HWn + c0 + k40) = tb0;
            *(float4*)(B + (size_t)m1 * HWn + c0 + k41) = tb1;
        }
        __syncthreads();
        if (ch < KCH / 32 - 1) {
            const int c1 = (ch + 1) * 32;
            ra0 = *(const float4*)(A + (size_t)m0 * HWn + c1 + k40);
            rb0 = *(const float4*)(B + (size_t)m0 * HWn + c1 + k40);
            ra1 = *(const float4*)(A + (size_t)m1 * HWn + c1 + k41);
            rb1 = *(const float4*)(B + (size_t)m1 * HWn + c1 + k41);
        }
        #pragma unroll
        for (int ks = 0; ks < 4; ks++) {
            const int kb = ks * 8;
            uint32_t a[2][4], b[4][2];
            #pragma unroll
            for (int mt = 0; mt < 2; mt++) {
                int m = mloc + mt * 16;
                a[mt][0] = FU(srcA[(m + g) * SA_STRIDE + kb + t4]);
                a[mt][1] = FU(srcA[(m + g + 8) * SA_STRIDE + kb + t4]);
                a[mt][2] = FU(srcA[(m + g) * SA_STRIDE + kb + t4 + 4]);
                a[mt][3] = FU(srcA[(m + g + 8) * SA_STRIDE + kb + t4 + 4]);
            }
            #pragma unroll
            for (int nt = 0; nt < 4; nt++) {
                int nn = wn * 32 + nt * 8;
                b[nt][0] = FU(sB[(nn + g) * SA_STRIDE + kb + t4]);
                b[nt][1] = FU(sB[(nn + g) * SA_STRIDE + kb + t4 + 4]);
            }
            #pragma unroll
            for (int mt = 0; mt < 2; mt++)
                #pragma unroll
                for (int nt = 0; nt < 4; nt++)
                    mma_tf32(acc[mt][nt], a[mt], b[nt]);
        }
        __syncthreads();
    }

    float* dst = g_xnp + (size_t)(n * SPLIT + sp) * 8192;
    #pragma unroll
    for (int mt = 0; mt < 2; mt++) {
        int r = wm * 32 + mt * 16 + g;
        #pragma unroll
        for (int nt = 0; nt < 4; nt++) {
            int t = wn * 32 + nt * 8 + 2 * t4;
            *(float2*)(dst + r * 64 + t)       = make_float2(acc[mt][nt][0], acc[mt][nt][1]);
            *(float2*)(dst + (r + 8) * 64 + t) = make_float2(acc[mt][nt][2], acc[mt][nt][3]);
        }
    }
}

// ================= k4f: fused GCN + M + BN partials ================
#define S68 68
#define K4F_SMEM ((3 * 64 * S68 + 128 * S68) * 4)   // 87040 B
__global__ void __launch_bounds__(256) k4f(
    const float* __restrict__ W1, const float* __restrict__ W2,
    const float* __restrict__ We)
{
    extern __shared__ float sm[];
    float* sXn = sm;
    float* sG  = sm + 64 * S68;
    float* sHT = sm + 2 * 64 * S68;
    float* sMb = sm + 3 * 64 * S68;
    const int n = blockIdx.x;
    const int tid = threadIdx.x, wid = tid >> 5, lane = tid & 31;
    const int g = lane >> 2, t4 = lane & 3;

    #pragma unroll
    for (int it = 0; it < 4; it++) {
        int idx = tid + it * 256;
        int row = idx >> 4, col = (idx & 15) * 4;
        float4 sx = {0.f,0.f,0.f,0.f}, sg = {0.f,0.f,0.f,0.f};
        #pragma unroll
        for (int p = 0; p < SPLIT; p++) {
            const float* base = g_xnp + (size_t)(n * SPLIT + p) * 8192;
            float4 a = *(const float4*)(base + row * 64 + col);
            float4 b = *(const float4*)(base + 4096 + row * 64 + col);
            sx.x += a.x; sx.y += a.y; sx.z += a.z; sx.w += a.w;
            sg.x += b.x; sg.y += b.y; sg.z += b.z; sg.w += b.w;
        }
        *(float4*)&sXn[row * S68 + col] = sx;
        *(float4*)&sG [row * S68 + col] = sg;
    }
    __syncthreads();

    {
        const int wm = wid >> 2, wn = wid & 3;
        float hacc[2][2][4] = {};
        #pragma unroll
        for (int ks = 0; ks < 8; ks++) {
            const int kb = ks * 8;
            uint32_t a[2][4], b[2][2];
            #pragma unroll
            for (int mt = 0; mt < 2; mt++) {
                int m = wm * 32 + mt * 16;
                a[mt][0] = FU(sXn[(m + g) * S68 + kb + t4]);
                a[mt][1] = FU(sXn[(m + g + 8) * S68 + kb + t4]);
                a[mt][2] = FU(sXn[(m + g) * S68 + kb + t4 + 4]);
                a[mt][3] = FU(sXn[(m + g + 8) * S68 + kb + t4 + 4]);
            }
            #pragma unroll
            for (int nt = 0; nt < 2; nt++) {
                int nn = wn * 16 + nt * 8;
                b[nt][0] = FU(__ldg(&W1[(nn + g) * 64 + kb + t4]));
                b[nt][1] = FU(__ldg(&W1[(nn + g) * 64 + kb + t4 + 4]));
            }
            #pragma unroll
            for (int mt = 0; mt < 2; mt++)
                #pragma unroll
                for (int nt = 0; nt < 2; nt++)
                    mma_tf32(hacc[mt][nt], a[mt], b[nt]);
        }
        #pragma unroll
        for (int mt = 0; mt < 2; mt++) {
            int s0 = wm * 32 + mt * 16 + g;
            #pragma unroll
            for (int nt = 0; nt < 2; nt++) {
                int i0 = wn * 16 + nt * 8 + 2 * t4;
                sHT[i0 * S68 + s0]           = hacc[mt][nt][0] - sXn[s0 * S68 + i0];
                sHT[(i0 + 1) * S68 + s0]     = hacc[mt][nt][1] - sXn[s0 * S68 + i0 + 1];
                sHT[i0 * S68 + s0 + 8]       = hacc[mt][nt][2] - sXn[(s0 + 8) * S68 + i0];
                sHT[(i0 + 1) * S68 + s0 + 8] = hacc[mt][nt][3] - sXn[(s0 + 8) * S68 + i0 + 1];
            }
        }
    }
    __syncthreads();

    {
        const int wm = wid >> 2, wn = wid & 3;
        float hacc[2][2][4] = {};
        #pragma unroll
        for (int ks = 0; ks < 8; ks++) {
            const int kb = ks * 8;
            uint32_t a[2][4], b[2][2];
            #pragma unroll
            for (int mt = 0; mt < 2; mt++) {
                int m = wm * 32 + mt * 16;
                a[mt][0] = FU(__ldg(&W2[(m + g) * 64 + kb + t4]));
                a[mt][1] = FU(__ldg(&W2[(m + g + 8) * 64 + kb + t4]));
                a[mt][2] = FU(__ldg(&W2[(m + g) * 64 + kb + t4 + 4]));
                a[mt][3] = FU(__ldg(&W2[(m + g + 8) * 64 + kb + t4 + 4]));
            }
            #pragma unroll
            for (int nt = 0; nt < 2; nt++) {
                int nn = wn * 16 + nt * 8;
                b[nt][0] = FU(sHT[(nn + g) * S68 + kb + t4]);
                b[nt][1] = FU(sHT[(nn + g) * S68 + kb + t4 + 4]);
            }
            #pragma unroll
            for (int mt = 0; mt < 2; mt++)
                #pragma unroll
                for (int nt = 0; nt < 2; nt++)
                    mma_tf32(hacc[mt][nt], a[mt], b[nt]);
        }
        __syncthreads();
        #pragma unroll
        for (int mt = 0; mt < 2; mt++) {
            int i0 = wm * 32 + mt * 16 + g;
            #pragma unroll
            for (int nt = 0; nt < 2; nt++) {
                int k = wn * 16 + nt * 8 + 2 * t4;
                sXn[i0 * S68 + k]           = fmaxf(hacc[mt][nt][0], 0.f);
                sXn[i0 * S68 + k + 1]       = fmaxf(hacc[mt][nt][1], 0.f);
                sXn[(i0 + 8) * S68 + k]     = fmaxf(hacc[mt][nt][2], 0.f);
                sXn[(i0 + 8) * S68 + k + 1] = fmaxf(hacc[mt][nt][3], 0.f);
            }
        }
    }
    __syncthreads();

    #pragma unroll 1
    for (int bnd = 0; bnd < 2; bnd++) {
        const int rloc = 16 * wid;
        const int c0 = bnd * 128 + rloc;
        float macc[8][4] = {}, racc[8][4] = {};
        #pragma unroll
        for (int ks = 0; ks < 8; ks++) {
            const int kb = ks * 8;
            uint32_t a[4], b[8][2];
            a[0] = FU(__ldg(&We[(c0 + g) * 64 + kb + t4]));
            a[1] = FU(__ldg(&We[(c0 + g + 8) * 64 + kb + t4]));
            a[2] = FU(__ldg(&We[(c0 + g) * 64 + kb + t4 + 4]));
            a[3] = FU(__ldg(&We[(c0 + g + 8) * 64 + kb + t4 + 4]));
            #pragma unroll
            for (int nt = 0; nt < 8; nt++) {
                b[nt][0] = FU(sXn[(kb + t4) * S68 + nt * 8 + g]);
                b[nt][1] = FU(sXn[(kb + t4 + 4) * S68 + nt * 8 + g]);
            }
            #pragma unroll
            for (int nt = 0; nt < 8; nt++)
                mma_tf32(macc[nt], a, b[nt]);
        }
        float* Mg = g_M + (size_t)n * Cc * Sn;
        #pragma unroll
        for (int nt = 0; nt < 8; nt++) {
            int col = nt * 8 + 2 * t4;
            *(float2*)(Mg + (c0 + g) * 64 + col)     = make_float2(macc[nt][0], macc[nt][1]);
            *(float2*)(Mg + (c0 + g + 8) * 64 + col) = make_float2(macc[nt][2], macc[nt][3]);
            sMb[(rloc + g) * S68 + col]     = macc[nt][0];
            sMb[(rloc + g) * S68 + col + 1] = macc[nt][1];
            sMb[(rloc + g + 8) * S68 + col]     = macc[nt][2];
            sMb[(rloc + g + 8) * S68 + col + 1] = macc[nt][3];
        }
        __syncthreads();
        #pragma unroll
        for (int ks = 0; ks < 8; ks++) {
            const int kb = ks * 8;
            uint32_t a[4], b[8][2];
            a[0] = FU(sMb[(rloc + g) * S68 + kb + t4]);
            a[1] = FU(sMb[(rloc + g + 8) * S68 + kb + t4]);
            a[2] = FU(sMb[(rloc + g) * S68 + kb + t4 + 4]);
            a[3] = FU(sMb[(rloc + g + 8) * S68 + kb + t4 + 4]);
            #pragma unroll
            for (int nt = 0; nt < 8; nt++) {
                b[nt][0] = FU(sG[(nt * 8 + g) * S68 + kb + t4]);
                b[nt][1] = FU(sG[(nt * 8 + g) * S68 + kb + t4 + 4]);
            }
            #pragma unroll
            for (int nt = 0; nt < 8; nt++)
                mma_tf32(racc[nt], a, b[nt]);
        }
        float s10 = 0.f, s11 = 0.f, s20 = 0.f, s21 = 0.f;
        #pragma unroll
        for (int nt = 0; nt < 8; nt++) {
            s10 += macc[nt][0] + macc[nt][1];
            s11 += macc[nt][2] + macc[nt][3];
            s20 += macc[nt][0] * racc[nt][0] + macc[nt][1] * racc[nt][1];
            s21 += macc[nt][2] * racc[nt][2] + macc[nt][3] * racc[nt][3];
        }
        s10 += __shfl_xor_sync(0xffffffffu, s10, 1); s10 += __shfl_xor_sync(0xffffffffu, s10, 2);
        s11 += __shfl_xor_sync(0xffffffffu, s11, 1); s11 += __shfl_xor_sync(0xffffffffu, s11, 2);
        s20 += __shfl_xor_sync(0xffffffffu, s20, 1); s20 += __shfl_xor_sync(0xffffffffu, s20, 2);
        s21 += __shfl_xor_sync(0xffffffffu, s21, 1); s21 += __shfl_xor_sync(0xffffffffu, s21, 2);
        if (t4 == 0) {
            g_s1[n * Cc + c0 + g] = s10;     g_s2[n * Cc + c0 + g] = s20;
            g_s1[n * Cc + c0 + g + 8] = s11; g_s2[n * Cc + c0 + g + 8] = s21;
        }
        __syncthreads();
    }
}

// ================= k7g: out = x + BN(M(128x64) @ comb-tile(64x128)) ==================
// R11 configuration; __launch_bounds__(256, 2) pins <=128 regs / 2 CTAs per SM.
__global__ void __launch_bounds__(256, 2) k7g_mma(
    const float* __restrict__ x, const float* __restrict__ gamma,
    const float* __restrict__ beta, float* __restrict__ out)
{
    extern __shared__ float smf[];
    float* sMean = smf + GEMM_SMEM_FLOATS;        // [128]
    float* sIstd = sMean + 128;                   // [128]
    const int n = blockIdx.z, band = blockIdx.y, tileX = blockIdx.x;
    const int r0 = band * 128, k0 = tileX * NT;
    const int tid = threadIdx.x, wid = tid >> 5, lane = tid & 31;
    const int wm = wid >> 2, wn = wid & 3;
    const int g = lane >> 2, t4 = lane & 3;
    const uint32_t sb = smem_u32(smf);
    float acc[4][4][4] = {};
    const float* Mb = g_M + (size_t)n * Cc * Sn;
    const float* Cb = g_t + (size_t)n * Sn * HWn + k0;

    #pragma unroll
    for (int ch = 0; ch < 2; ch++) {
        const uint32_t base = sb + (ch ? OFF_A1 : OFF_A0) * 4;
        #pragma unroll
        for (int it = 0; it < 4; it++) {
            int idx = tid + it * 256;
            int m = idx >> 3, k4 = idx & 7;
            cp16(base + (uint32_t)(m * SA_STRIDE + k4 * 4) * 4,
                 Mb + (size_t)(r0 + m) * 64 + ch * 32 + k4 * 4);
        }
    }
    #pragma unroll
    for (int ch = 0; ch < 2; ch++) {
        const uint32_t base = sb + (ch ? OFF_B1 : OFF_B0) * 4;
        #pragma unroll
        for (int it = 0; it < 4; it++) {
            int idx = tid + it * 256;
            int k = idx >> 5, n4 = idx & 31;
            cp16(base + (uint32_t)(k * SB_STRIDE + n4 * 4) * 4,
                 Cb + (size_t)(ch * 32 + k) * HWn + n4 * 4);
        }
    }
    CP_COMMIT();
    if (tid < 128) {
        int c = r0 + tid;
        float s = 0.f, q = 0.f;
        #pragma unroll
        for (int nn = 0; nn < Nn; nn++) { s += g_s1[nn * Cc + c]; q += g_s2[nn * Cc + c]; }
        float mean = s / CNT;
        float var = q / CNT - mean * mean;
        sMean[tid] = mean;
        sIstd[tid] = rsqrtf(var + 1e-5f);
    }
    CP_WAIT0();
    __syncthreads();

    #pragma unroll
    for (int ch = 0; ch < 2; ch++) {
        const float* fA = smf + (ch ? OFF_A1 : OFF_A0);
        const float* fB = smf + (ch ? OFF_B1 : OFF_B0);
        #pragma unroll
        for (int ks = 0; ks < 4; ks++) {
            const int kb = ks * 8;
            uint32_t a[4][4], b[4][2];
            #pragma unroll
            for (int mt = 0; mt < 4; mt++) {
                int m = wm * 64 + mt * 16;
                a[mt][0] = FU(fA[(m + g) * SA_STRIDE + kb + t4]);
                a[mt][1] = FU(fA[(m + g + 8) * SA_STRIDE + kb + t4]);
                a[mt][2] = FU(fA[(m + g) * SA_STRIDE + kb + t4 + 4]);
                a[mt][3] = FU(fA[(m + g + 8) * SA_STRIDE + kb + t4 + 4]);
            }
            #pragma unroll
            for (int nt = 0; nt < 4; nt++) {
                int nn = wn * 32 + nt * 8;
                b[nt][0] = FU(fB[(kb + t4) * SB_STRIDE + nn + g]);
                b[nt][1] = FU(fB[(kb + t4 + 4) * SB_STRIDE + nn + g]);
            }
            #pragma unroll
            for (int mt = 0; mt < 4; mt++)
                #pragma unroll
                for (int nt = 0; nt < 4; nt++)
                    mma_tf32(acc[mt][nt], a[mt], b[nt]);
        }
    }

    const int nbase = k0 + wn * 32 + 2 * t4;
    #pragma unroll
    for (int mt = 0; mt < 4; mt++) {
        int lA = wm * 64 + mt * 16 + g;
        int cA = r0 + lA, cB = cA + 8;
        float gA = gamma[cA] * sIstd[lA],     bA = beta[cA] - sMean[lA] * gA;
        float gB = gamma[cB] * sIstd[lA + 8], bB = beta[cB] - sMean[lA + 8] * gB;
        const float* x0p = x + (size_t)(n * Cc + cA) * HWn;
        const float* x1p = x0p + (size_t)8 * HWn;
        float* o0p = out + (size_t)(n * Cc + cA) * HWn;
        float* o1p = o0p + (size_t)8 * HWn;
        #pragma unroll
        for (int nt = 0; nt < 4; nt++) {
            int col = nbase + nt * 8;
            float2 xv0 = *(const float2*)(x0p + col);
            float2 xv1 = *(const float2*)(x1p + col);
            *(float2*)(o0p + col) = make_float2(xv0.x + acc[mt][nt][0] * gA + bA,
                                                xv0.y + acc[mt][nt][1] * gA + bA);
            *(float2*)(o1p + col) = make_float2(xv1.x + acc[mt][nt][2] * gB + bB,
                                                xv1.y + acc[mt][nt][3] * gB + bB);
        }
    }
}

// ---------------- launch ----------------
extern "C" void kernel_launch(void* const* d_in, const int* in_sizes, int n_in,
                              void* d_out, int out_size)
{
    const float* x     = (const float*)d_in[0];
    const float* edge  = (const float*)d_in[1];
    const float* Ws    = (const float*)d_in[2];
    const float* bs    = (const float*)d_in[3];
    const float* Wp    = (const float*)d_in[4];
    const float* bp    = (const float*)d_in[5];
    const float* W1    = (const float*)d_in[6];
    const float* W2    = (const float*)d_in[7];
    const float* We    = (const float*)d_in[8];
    const float* gamma = (const float*)d_in[9];
    const float* beta  = (const float*)d_in[10];
    float* out = (float*)d_out;

    cudaFuncSetAttribute(k1_mma,  cudaFuncAttributeMaxDynamicSharedMemorySize, K1_SMEM_BYTES);
    cudaFuncSetAttribute(k4f,     cudaFuncAttributeMaxDynamicSharedMemorySize, K4F_SMEM);
    cudaFuncSetAttribute(k7g_mma, cudaFuncAttributeMaxDynamicSharedMemorySize, K7_SMEM_BYTES);

    k1_mma <<<dim3(NTILE, Nn), 256, K1_SMEM_BYTES>>>(x, edge, Ws, bs, Wp, bp);
    k3g_mma<<<dim3(SPLIT, Nn), 256>>>();
    k4f    <<<Nn, 256, K4F_SMEM>>>(W1, W2, We);
    k7g_mma<<<dim3(NTILE, 2, Nn), 256, K7_SMEM_BYTES>>>(x, gamma, beta, out);
}